// round 3
// baseline (speedup 1.0000x reference)
#include <cuda_runtime.h>
#include <cuda_bf16.h>
#include <cstdint>

// ============================================================================
// SimpleRNN fused kernel, baseline-PTX version (mma.sync bf16 + ldmatrix).
//   h_{t+1} = tanh(x_t@W_ih^T + b + h_t@W_hh^T), t=0..27;  out = h@W_fc^T + b_fc
// Grid: 128 CTAs x 256 threads; CTA = 128 batch rows. Warp grid 4m x 2n
// (warp tile M=32, N=64). 3-term bf16 hi/lo split GEMM for fp32-like accuracy.
// ============================================================================

#define SM_WHH_HI 0          // 128 x 128 bf16, row stride 256B, swz ^(row&7)
#define SM_WHH_LO 32768
#define SM_WIH_HI 65536      // 128 x 32 bf16, row stride 64B, swz ^(row&3)
#define SM_WIH_LO 73728
#define SM_H_HI   81920      // 128 x 128 bf16 (A operand of hh GEMM)
#define SM_H_LO   114688
#define SM_X_HI   147456     // 128 x 32 bf16 (A operand of x GEMM)
#define SM_X_LO   155648
#define SM_WFC    163840     // 10 x 128 fp32
#define SM_BFC    168960     // 10 fp32 (+pad)
#define SM_TOTAL  169472
// post-loop alias: fp32 h28 at offset 0, row stride 132 floats (528B)

static __device__ __forceinline__ uint32_t s2u(const void* p) {
    uint32_t a;
    asm("{ .reg .u64 t; cvta.to.shared.u64 t, %1; cvt.u32.u64 %0, t; }"
        : "=r"(a) : "l"(p));
    return a;
}

// pack two floats -> bf16x2, v0 in low half (lower address / first K element)
static __device__ __forceinline__ uint32_t packbf(float v0, float v1) {
    uint32_t r;
    asm("cvt.rn.bf16x2.f32 %0, %1, %2;" : "=r"(r) : "f"(v1), "f"(v0));
    return r;
}

// accurate tanh: 1 - 2/(e^{2x}+1)  (~1e-7 abs err)
static __device__ __forceinline__ float tanh_acc(float v) {
    float a = fminf(fmaxf(v * 2.885390082f, -30.0f), 30.0f);  // 2x * log2(e)
    float e; asm("ex2.approx.f32 %0, %1;" : "=f"(e) : "f"(a));
    float r; asm("rcp.approx.f32 %0, %1;" : "=f"(r) : "f"(e + 1.0f));
    return fmaf(-2.0f, r, 1.0f);
}

#define LDSM4(R, A)                                                         \
    asm volatile("ldmatrix.sync.aligned.m8n8.x4.shared.b16 {%0,%1,%2,%3}, [%4];" \
                 : "=r"((R)[0]), "=r"((R)[1]), "=r"((R)[2]), "=r"((R)[3])   \
                 : "r"(A))

static __device__ __forceinline__ void mma_bf16(float* d, const uint32_t* a,
                                                uint32_t b0, uint32_t b1) {
    asm volatile(
        "mma.sync.aligned.m16n8k16.row.col.f32.bf16.bf16.f32 "
        "{%0,%1,%2,%3}, {%4,%5,%6,%7}, {%8,%9}, {%0,%1,%2,%3};"
        : "+f"(d[0]), "+f"(d[1]), "+f"(d[2]), "+f"(d[3])
        : "r"(a[0]), "r"(a[1]), "r"(a[2]), "r"(a[3]), "r"(b0), "r"(b1));
}

// split fp32 -> bf16 hi + residual lo, write pair to two buffers
static __device__ __forceinline__ void split_store(char* smem, uint32_t off_hi,
                                                   uint32_t off_lo, uint32_t byte,
                                                   float v0, float v1) {
    uint32_t p = packbf(v0, v1);
    float f0 = __uint_as_float(p << 16);
    float f1 = __uint_as_float(p & 0xFFFF0000u);
    *(uint32_t*)(smem + off_hi + byte) = p;
    *(uint32_t*)(smem + off_lo + byte) = packbf(v0 - f0, v1 - f1);
}

// store one row of x (K=32: 28 vals + bias-1 col + zeros) as split bf16
static __device__ __forceinline__ void store_x_row(char* smem, int r, int half,
                                                   const float* xf) {
    const int r3 = r & 3;
    if (half == 0) {
        #pragma unroll
        for (int p = 0; p < 8; p++) {
            uint32_t byte = (uint32_t)(r * 64 + (((p >> 2) ^ r3) << 4) + ((4 * p) & 15));
            split_store(smem, SM_X_HI, SM_X_LO, byte, xf[2 * p], xf[2 * p + 1]);
        }
    } else {
        #pragma unroll
        for (int q = 0; q < 6; q++) {
            int p = 8 + q;
            uint32_t byte = (uint32_t)(r * 64 + (((p >> 2) ^ r3) << 4) + ((4 * p) & 15));
            split_store(smem, SM_X_HI, SM_X_LO, byte, xf[2 * q], xf[2 * q + 1]);
        }
        // pair 14: cols 28,29 = (1.0, 0) bias column; pair 15: zeros
        uint32_t b14 = (uint32_t)(r * 64 + (((14 >> 2) ^ r3) << 4) + ((4 * 14) & 15));
        uint32_t b15 = (uint32_t)(r * 64 + (((15 >> 2) ^ r3) << 4) + ((4 * 15) & 15));
        *(uint32_t*)(smem + SM_X_HI + b14) = packbf(1.0f, 0.0f);
        *(uint32_t*)(smem + SM_X_LO + b14) = 0u;
        *(uint32_t*)(smem + SM_X_HI + b15) = 0u;
        *(uint32_t*)(smem + SM_X_LO + b15) = 0u;
    }
}

__global__ void __launch_bounds__(256, 1) SimpleRNN_fused_kernel(
    const float* __restrict__ x,    // [16384,1,28,28]
    const float* __restrict__ Wih,  // [128,28]
    const float* __restrict__ Whh,  // [128,128]
    const float* __restrict__ bih,  // [128]
    const float* __restrict__ bhh,  // [128]
    const float* __restrict__ Wfc,  // [10,128]
    const float* __restrict__ bfc,  // [10]
    float* __restrict__ out)        // [16384,10]
{
    extern __shared__ char smem[];
    const uint32_t sb = s2u(smem);
    const int tid  = threadIdx.x;
    const int lane = tid & 31;
    const int wid  = tid >> 5;
    const int m0 = (wid & 3) * 32;   // warp M offset
    const int n0 = (wid >> 2) * 64;  // warp N offset

    // lane-derived ldmatrix addressing constants
    const int rowA = lane & 15;                       // A: row within 16-tile
    const int csA  = lane >> 4;                       // A: k-half (0/1)
    const int rowB = ((lane >> 4) << 3) | (lane & 7); // B: row within 16 n-rows
    const int csB  = (lane >> 3) & 1;                 // B: k-half
    const int l7 = lane & 7, l3 = lane & 3;

    // ---- one-time: convert weights to split-bf16 swizzled SMEM tiles ----
    for (int i = tid; i < 128 * 128; i += 256) {
        int n = i >> 7, k = i & 127;
        float v = Whh[i];
        uint32_t p = packbf(v, 0.0f) & 0xFFFFu;  // low half holds bf16(v)
        float fh = __uint_as_float(p << 16);
        uint32_t pl = packbf(v - fh, 0.0f) & 0xFFFFu;
        uint32_t byte = (uint32_t)(n * 256 + (((k >> 3) ^ (n & 7)) << 4) + (k & 7) * 2);
        *(uint16_t*)(smem + SM_WHH_HI + byte) = (uint16_t)p;
        *(uint16_t*)(smem + SM_WHH_LO + byte) = (uint16_t)pl;
    }
    for (int i = tid; i < 128 * 32; i += 256) {
        int n = i >> 5, k = i & 31;
        float v = (k < 28) ? Wih[n * 28 + k] : ((k == 28) ? (bih[n] + bhh[n]) : 0.0f);
        uint32_t p = packbf(v, 0.0f) & 0xFFFFu;
        float fh = __uint_as_float(p << 16);
        uint32_t pl = packbf(v - fh, 0.0f) & 0xFFFFu;
        uint32_t byte = (uint32_t)(n * 64 + (((k >> 3) ^ (n & 3)) << 4) + (k & 7) * 2);
        *(uint16_t*)(smem + SM_WIH_HI + byte) = (uint16_t)p;
        *(uint16_t*)(smem + SM_WIH_LO + byte) = (uint16_t)pl;
    }
    for (int i = tid; i < 1280; i += 256) ((float*)(smem + SM_WFC))[i] = Wfc[i];
    if (tid < 10) ((float*)(smem + SM_BFC))[tid] = bfc[tid];

    // ---- x(0) prefetch + store ----
    const int xr = tid >> 1, xhalf = tid & 1;
    const size_t xbase = ((size_t)blockIdx.x * 128 + xr) * 784 + (size_t)xhalf * 16;
    float xf[16];
    {
        const float4* px = (const float4*)(x + xbase);
        #pragma unroll
        for (int q = 0; q < 4; q++) {
            if (xhalf == 0 || q < 3) { float4 v = px[q];
                xf[4*q] = v.x; xf[4*q+1] = v.y; xf[4*q+2] = v.z; xf[4*q+3] = v.w; }
        }
        store_x_row(smem, xr, xhalf, xf);
    }
    __syncthreads();

    float acc[2][8][4];

    #pragma unroll 1
    for (int t = 0; t < 28; t++) {
        #pragma unroll
        for (int mt = 0; mt < 2; mt++)
            #pragma unroll
            for (int nt = 0; nt < 8; nt++)
                #pragma unroll
                for (int j = 0; j < 4; j++) acc[mt][nt][j] = 0.0f;

        // ---- x GEMM terms (K=32) ----
        #pragma unroll
        for (int kt = 0; kt < 2; kt++) {
            uint32_t Ah[2][4], Al[2][4], Bh[4][4], Bl[4][4];
            #pragma unroll
            for (int mt = 0; mt < 2; mt++) {
                uint32_t ro = (uint32_t)((m0 + mt * 16 + rowA) * 64 + (((kt * 2 + csA) ^ l3) << 4));
                LDSM4(Ah[mt], sb + SM_X_HI + ro);
                LDSM4(Al[mt], sb + SM_X_LO + ro);
            }
            #pragma unroll
            for (int nt2 = 0; nt2 < 4; nt2++) {
                uint32_t ro = (uint32_t)((n0 + nt2 * 16 + rowB) * 64 + (((kt * 2 + csB) ^ l3) << 4));
                LDSM4(Bh[nt2], sb + SM_WIH_HI + ro);
                LDSM4(Bl[nt2], sb + SM_WIH_LO + ro);
            }
            #pragma unroll
            for (int mt = 0; mt < 2; mt++)
                #pragma unroll
                for (int nt2 = 0; nt2 < 4; nt2++) {
                    mma_bf16(acc[mt][2*nt2],   Ah[mt], Bh[nt2][0], Bh[nt2][1]);
                    mma_bf16(acc[mt][2*nt2+1], Ah[mt], Bh[nt2][2], Bh[nt2][3]);
                    mma_bf16(acc[mt][2*nt2],   Ah[mt], Bl[nt2][0], Bl[nt2][1]);
                    mma_bf16(acc[mt][2*nt2+1], Ah[mt], Bl[nt2][2], Bl[nt2][3]);
                    mma_bf16(acc[mt][2*nt2],   Al[mt], Bh[nt2][0], Bh[nt2][1]);
                    mma_bf16(acc[mt][2*nt2+1], Al[mt], Bh[nt2][2], Bh[nt2][3]);
                }
        }

        // ---- hh GEMM terms (K=128), skipped at t=0 (h=0) ----
        if (t > 0) {
            #pragma unroll
            for (int kt = 0; kt < 8; kt++) {
                uint32_t Ah[2][4], Al[2][4], Bh[4][4], Bl[4][4];
                #pragma unroll
                for (int mt = 0; mt < 2; mt++) {
                    uint32_t ro = (uint32_t)((m0 + mt * 16 + rowA) * 256 + (((kt * 2 + csA) ^ l7) << 4));
                    LDSM4(Ah[mt], sb + SM_H_HI + ro);
                    LDSM4(Al[mt], sb + SM_H_LO + ro);
                }
                #pragma unroll
                for (int nt2 = 0; nt2 < 4; nt2++) {
                    uint32_t ro = (uint32_t)((n0 + nt2 * 16 + rowB) * 256 + (((kt * 2 + csB) ^ l7) << 4));
                    LDSM4(Bh[nt2], sb + SM_WHH_HI + ro);
                    LDSM4(Bl[nt2], sb + SM_WHH_LO + ro);
                }
                #pragma unroll
                for (int mt = 0; mt < 2; mt++)
                    #pragma unroll
                    for (int nt2 = 0; nt2 < 4; nt2++) {
                        mma_bf16(acc[mt][2*nt2],   Ah[mt], Bh[nt2][0], Bh[nt2][1]);
                        mma_bf16(acc[mt][2*nt2+1], Ah[mt], Bh[nt2][2], Bh[nt2][3]);
                        mma_bf16(acc[mt][2*nt2],   Ah[mt], Bl[nt2][0], Bl[nt2][1]);
                        mma_bf16(acc[mt][2*nt2+1], Ah[mt], Bl[nt2][2], Bl[nt2][3]);
                        mma_bf16(acc[mt][2*nt2],   Al[mt], Bh[nt2][0], Bh[nt2][1]);
                        mma_bf16(acc[mt][2*nt2+1], Al[mt], Bh[nt2][2], Bh[nt2][3]);
                    }
            }
        }

        // prefetch x(t+1) under the tail of the MMA phase
        if (t < 27) {
            const float4* px = (const float4*)(x + xbase + (size_t)(t + 1) * 28);
            #pragma unroll
            for (int q = 0; q < 4; q++) {
                if (xhalf == 0 || q < 3) { float4 v = px[q];
                    xf[4*q] = v.x; xf[4*q+1] = v.y; xf[4*q+2] = v.z; xf[4*q+3] = v.w; }
            }
        }

        __syncthreads();  // all warps done reading h(t), x(t)

        if (t < 27) {
            // h(t+1) = tanh(acc) -> split bf16 into H buffers
            #pragma unroll
            for (int mt = 0; mt < 2; mt++)
                #pragma unroll
                for (int nt = 0; nt < 8; nt++) {
                    const float* c = acc[mt][nt];
                    int r0 = m0 + mt * 16 + (lane >> 2);
                    int col = n0 + nt * 8 + (lane & 3) * 2;
                    int chunk = (n0 >> 3) + nt;
                    uint32_t b0 = (uint32_t)(r0 * 256 + ((chunk ^ (r0 & 7)) << 4) + (lane & 3) * 4);
                    int r1 = r0 + 8;
                    uint32_t b1 = (uint32_t)(r1 * 256 + ((chunk ^ (r1 & 7)) << 4) + (lane & 3) * 4);
                    (void)col;
                    split_store(smem, SM_H_HI, SM_H_LO, b0, tanh_acc(c[0]), tanh_acc(c[1]));
                    split_store(smem, SM_H_HI, SM_H_LO, b1, tanh_acc(c[2]), tanh_acc(c[3]));
                }
            store_x_row(smem, xr, xhalf, xf);
        } else {
            // final h28 in fp32, aliased over dead W_hh region (stride 132 floats)
            float* h32 = (float*)smem;
            #pragma unroll
            for (int mt = 0; mt < 2; mt++)
                #pragma unroll
                for (int nt = 0; nt < 8; nt++) {
                    const float* c = acc[mt][nt];
                    int r0 = m0 + mt * 16 + (lane >> 2);
                    int col = n0 + nt * 8 + (lane & 3) * 2;
                    *(float2*)(h32 + r0 * 132 + col)       = make_float2(tanh_acc(c[0]), tanh_acc(c[1]));
                    *(float2*)(h32 + (r0 + 8) * 132 + col) = make_float2(tanh_acc(c[2]), tanh_acc(c[3]));
                }
        }
        __syncthreads();
    }

    // ---- fc: out = h28 @ W_fc^T + b_fc (fp32 SIMT) ----
    {
        const float* h32 = (const float*)smem;
        const float* wfc = (const float*)(smem + SM_WFC);
        const float* bfcS = (const float*)(smem + SM_BFC);
        int r = tid >> 1;
        int c0 = (tid & 1) * 5;
        float s[5];
        #pragma unroll
        for (int j = 0; j < 5; j++) s[j] = bfcS[c0 + j];
        const float4* hr = (const float4*)(h32 + r * 132);
        #pragma unroll 8
        for (int k4 = 0; k4 < 32; k4++) {
            float4 hv = hr[k4];
            #pragma unroll
            for (int j = 0; j < 5; j++) {
                float4 wv = ((const float4*)(wfc + (c0 + j) * 128))[k4];
                s[j] += hv.x * wv.x + hv.y * wv.y + hv.z * wv.z + hv.w * wv.w;
            }
        }
        float* o = out + ((size_t)blockIdx.x * 128 + r) * 10 + c0;
        #pragma unroll
        for (int j = 0; j < 5; j++) o[j] = s[j];
    }
}

extern "C" void kernel_launch(void* const* d_in, const int* in_sizes, int n_in,
                              void* d_out, int out_size) {
    const float* x   = (const float*)d_in[0];
    const float* Wih = (const float*)d_in[1];
    const float* Whh = (const float*)d_in[2];
    const float* bih = (const float*)d_in[3];
    const float* bhh = (const float*)d_in[4];
    const float* Wfc = (const float*)d_in[5];
    const float* bfc = (const float*)d_in[6];
    float* out = (float*)d_out;

    cudaFuncSetAttribute(SimpleRNN_fused_kernel,
                         cudaFuncAttributeMaxDynamicSharedMemorySize, SM_TOTAL);
    SimpleRNN_fused_kernel<<<128, 256, SM_TOTAL>>>(x, Wih, Whh, bih, bhh, Wfc, bfc, out);
}

// round 4
// speedup vs baseline: 1.8283x; 1.8283x over previous
#include <cuda_runtime.h>
#include <cuda_fp16.h>
#include <cstdint>

// ============================================================================
// SimpleRNN fused kernel: single-term fp16 mma.sync (m16n8k16), fp32 accum.
//   h_{t+1} = tanh(x_t@W_ih^T + b + h_t@W_hh^T), t=0..27; out = h@W_fc^T + b_fc
// Grid: 128 CTAs x 512 threads; CTA = 128 batch rows. Warp grid 4m x 4n
// (warp tile 32x32). Error anchor from R3: per-GEMM input err 2^-16 -> final
// 5.1e-6; fp16 (2^-11) predicts ~1.6e-4 final, under the 1e-3 gate.
// ============================================================================

#define SM_WHH 0          // 128 x 128 fp16, row stride 256B, swz ^(row&7)
#define SM_WIH 32768      // 128 x 32 fp16, row stride 64B, swz ^(row&3)
#define SM_H   40960      // 128 x 128 fp16 (A of hh GEMM)
#define SM_X   73728      // 128 x 32 fp16 (A of x GEMM; col28 = bias 1.0)
#define SM_WFC 81920      // 10 x 128 fp32
#define SM_BFC 87040      // 10 fp32
#define SM_TOTAL 87168
// post-loop alias: fp32 h28 at offset 0, row stride 132 floats (< SM_WFC)

static __device__ __forceinline__ uint32_t s2u(const void* p) {
    uint32_t a;
    asm("{ .reg .u64 t; cvta.to.shared.u64 t, %1; cvt.u32.u64 %0, t; }"
        : "=r"(a) : "l"(p));
    return a;
}

// pack two floats -> fp16x2, v0 in low half (first K/col element)
static __device__ __forceinline__ uint32_t packh(float v0, float v1) {
    uint32_t r;
    asm("cvt.rn.f16x2.f32 %0, %1, %2;" : "=r"(r) : "f"(v1), "f"(v0));
    return r;
}

// accurate tanh: 1 - 2/(e^{2x}+1)  (~1e-7 abs err)
static __device__ __forceinline__ float tanh_acc(float v) {
    float a = fminf(fmaxf(v * 2.885390082f, -30.0f), 30.0f);  // 2x * log2(e)
    float e; asm("ex2.approx.f32 %0, %1;" : "=f"(e) : "f"(a));
    float r; asm("rcp.approx.f32 %0, %1;" : "=f"(r) : "f"(e + 1.0f));
    return fmaf(-2.0f, r, 1.0f);
}

#define LDSM4(R, A)                                                              \
    asm volatile("ldmatrix.sync.aligned.m8n8.x4.shared.b16 {%0,%1,%2,%3}, [%4];" \
                 : "=r"((R)[0]), "=r"((R)[1]), "=r"((R)[2]), "=r"((R)[3])        \
                 : "r"(A))

static __device__ __forceinline__ void mma_f16(float* d, const uint32_t* a,
                                               uint32_t b0, uint32_t b1) {
    asm volatile(
        "mma.sync.aligned.m16n8k16.row.col.f32.f16.f16.f32 "
        "{%0,%1,%2,%3}, {%4,%5,%6,%7}, {%8,%9}, {%0,%1,%2,%3};"
        : "+f"(d[0]), "+f"(d[1]), "+f"(d[2]), "+f"(d[3])
        : "r"(a[0]), "r"(a[1]), "r"(a[2]), "r"(a[3]), "r"(b0), "r"(b1));
}

__global__ void __launch_bounds__(512, 1) SimpleRNN_fused_kernel(
    const float* __restrict__ x,    // [16384,1,28,28]
    const float* __restrict__ Wih,  // [128,28]
    const float* __restrict__ Whh,  // [128,128]
    const float* __restrict__ bih,  // [128]
    const float* __restrict__ bhh,  // [128]
    const float* __restrict__ Wfc,  // [10,128]
    const float* __restrict__ bfc,  // [10]
    float* __restrict__ out)        // [16384,10]
{
    extern __shared__ char smem[];
    const uint32_t sb = s2u(smem);
    const int tid  = threadIdx.x;
    const int lane = tid & 31;
    const int wid  = tid >> 5;
    const int m0 = (wid & 3) * 32;   // warp M offset
    const int n0 = (wid >> 2) * 32;  // warp N offset

    // ldmatrix lane addressing
    const int rowA = lane & 15;                       // A row within m16 tile
    const int csA  = lane >> 4;                       // A k-half
    const int rowB = ((lane >> 4) << 3) | (lane & 7); // B row within n16 rows
    const int csB  = (lane >> 3) & 1;                 // B k-half
    const int l7 = lane & 7, l3 = lane & 3;

    // ---- one-time: weights -> fp16 swizzled SMEM ----
    for (int i = tid; i < 128 * 128; i += 512) {
        int n = i >> 7, k = i & 127;
        uint32_t byte = (uint32_t)(n * 256 + (((k >> 3) ^ (n & 7)) << 4) + (k & 7) * 2);
        *(uint16_t*)(smem + SM_WHH + byte) = __half_as_ushort(__float2half_rn(Whh[i]));
    }
    for (int i = tid; i < 128 * 32; i += 512) {
        int n = i >> 5, k = i & 31;
        float v = (k < 28) ? Wih[n * 28 + k] : ((k == 28) ? (bih[n] + bhh[n]) : 0.0f);
        uint32_t byte = (uint32_t)(n * 64 + (((k >> 3) ^ (n & 3)) << 4) + (k & 7) * 2);
        *(uint16_t*)(smem + SM_WIH + byte) = __half_as_ushort(__float2half_rn(v));
    }
    for (int i = tid; i < 1280; i += 512) ((float*)(smem + SM_WFC))[i] = Wfc[i];
    if (tid < 10) ((float*)(smem + SM_BFC))[tid] = bfc[tid];

    // ---- x layout: thread handles row r = tid>>2, col chunk q = tid&3 ----
    const int xr = tid >> 2, xq = tid & 3;
    const size_t xbase = ((size_t)blockIdx.x * 128 + xr) * 784 + (size_t)xq * 8;
    const uint32_t xaddr = sb + SM_X + (uint32_t)(xr * 64 + ((xq ^ (xr & 3)) << 4));
    float xf[8];
    {
        const float4* px = (const float4*)(x + xbase);
        float4 v0 = px[0];
        xf[0]=v0.x; xf[1]=v0.y; xf[2]=v0.z; xf[3]=v0.w;
        if (xq < 3) { float4 v1 = px[1]; xf[4]=v1.x; xf[5]=v1.y; xf[6]=v1.z; xf[7]=v1.w; }
    }
    {
        uint32_t p0 = packh(xf[0], xf[1]), p1 = packh(xf[2], xf[3]);
        uint32_t p2, p3;
        if (xq < 3) { p2 = packh(xf[4], xf[5]); p3 = packh(xf[6], xf[7]); }
        else        { p2 = 0x00003C00u; p3 = 0u; }  // cols 28=1.0(bias),29..31=0
        asm volatile("st.shared.v4.b32 [%0], {%1,%2,%3,%4};"
                     :: "r"(xaddr), "r"(p0), "r"(p1), "r"(p2), "r"(p3) : "memory");
    }
    __syncthreads();

    float acc[2][4][4];

    #pragma unroll 1
    for (int t = 0; t < 28; t++) {
        #pragma unroll
        for (int mt = 0; mt < 2; mt++)
            #pragma unroll
            for (int nt = 0; nt < 4; nt++)
                #pragma unroll
                for (int j = 0; j < 4; j++) acc[mt][nt][j] = 0.0f;

        // ---- x GEMM (K=32) ----
        #pragma unroll
        for (int kt = 0; kt < 2; kt++) {
            uint32_t A[2][4], B[2][4];
            #pragma unroll
            for (int mt = 0; mt < 2; mt++) {
                uint32_t ro = (uint32_t)((m0 + mt * 16 + rowA) * 64 + (((kt * 2 + csA) ^ l3) << 4));
                LDSM4(A[mt], sb + SM_X + ro);
            }
            #pragma unroll
            for (int nt = 0; nt < 2; nt++) {
                uint32_t ro = (uint32_t)((n0 + nt * 16 + rowB) * 64 + (((kt * 2 + csB) ^ l3) << 4));
                LDSM4(B[nt], sb + SM_WIH + ro);
            }
            #pragma unroll
            for (int mt = 0; mt < 2; mt++)
                #pragma unroll
                for (int nt = 0; nt < 2; nt++) {
                    mma_f16(acc[mt][2*nt],   A[mt], B[nt][0], B[nt][1]);
                    mma_f16(acc[mt][2*nt+1], A[mt], B[nt][2], B[nt][3]);
                }
        }

        // ---- hh GEMM (K=128), skip at t=0 (h=0) ----
        if (t > 0) {
            #pragma unroll
            for (int kt = 0; kt < 8; kt++) {
                uint32_t A[2][4], B[2][4];
                #pragma unroll
                for (int mt = 0; mt < 2; mt++) {
                    uint32_t ro = (uint32_t)((m0 + mt * 16 + rowA) * 256 + (((kt * 2 + csA) ^ l7) << 4));
                    LDSM4(A[mt], sb + SM_H + ro);
                }
                #pragma unroll
                for (int nt = 0; nt < 2; nt++) {
                    uint32_t ro = (uint32_t)((n0 + nt * 16 + rowB) * 256 + (((kt * 2 + csB) ^ l7) << 4));
                    LDSM4(B[nt], sb + SM_WHH + ro);
                }
                #pragma unroll
                for (int mt = 0; mt < 2; mt++)
                    #pragma unroll
                    for (int nt = 0; nt < 2; nt++) {
                        mma_f16(acc[mt][2*nt],   A[mt], B[nt][0], B[nt][1]);
                        mma_f16(acc[mt][2*nt+1], A[mt], B[nt][2], B[nt][3]);
                    }
            }
        }

        // prefetch x(t+1) under the MMA tail
        if (t < 27) {
            const float4* px = (const float4*)(x + xbase + (size_t)(t + 1) * 28);
            float4 v0 = px[0];
            xf[0]=v0.x; xf[1]=v0.y; xf[2]=v0.z; xf[3]=v0.w;
            if (xq < 3) { float4 v1 = px[1]; xf[4]=v1.x; xf[5]=v1.y; xf[6]=v1.z; xf[7]=v1.w; }
        }

        __syncthreads();  // all warps done reading h(t), x(t)

        if (t < 27) {
            // h(t+1) = tanh(acc) -> fp16 into H
            #pragma unroll
            for (int mt = 0; mt < 2; mt++)
                #pragma unroll
                for (int nt = 0; nt < 4; nt++) {
                    const float* c = acc[mt][nt];
                    int r0 = m0 + mt * 16 + (lane >> 2);
                    int r1 = r0 + 8;
                    int chunk = (n0 >> 3) + nt;
                    uint32_t b0 = (uint32_t)(r0 * 256 + ((chunk ^ (r0 & 7)) << 4) + (lane & 3) * 4);
                    uint32_t b1 = (uint32_t)(r1 * 256 + ((chunk ^ (r1 & 7)) << 4) + (lane & 3) * 4);
                    *(uint32_t*)(smem + SM_H + b0) = packh(tanh_acc(c[0]), tanh_acc(c[1]));
                    *(uint32_t*)(smem + SM_H + b1) = packh(tanh_acc(c[2]), tanh_acc(c[3]));
                }
            // store x(t+1)
            uint32_t p0 = packh(xf[0], xf[1]), p1 = packh(xf[2], xf[3]);
            uint32_t p2, p3;
            if (xq < 3) { p2 = packh(xf[4], xf[5]); p3 = packh(xf[6], xf[7]); }
            else        { p2 = 0x00003C00u; p3 = 0u; }
            asm volatile("st.shared.v4.b32 [%0], {%1,%2,%3,%4};"
                         :: "r"(xaddr), "r"(p0), "r"(p1), "r"(p2), "r"(p3) : "memory");
        } else {
            // final h28 in fp32, aliased at smem offset 0 (stride 132 floats)
            float* h32 = (float*)smem;
            #pragma unroll
            for (int mt = 0; mt < 2; mt++)
                #pragma unroll
                for (int nt = 0; nt < 4; nt++) {
                    const float* c = acc[mt][nt];
                    int r0 = m0 + mt * 16 + (lane >> 2);
                    int col = n0 + nt * 8 + (lane & 3) * 2;
                    *(float2*)(h32 + r0 * 132 + col)       = make_float2(tanh_acc(c[0]), tanh_acc(c[1]));
                    *(float2*)(h32 + (r0 + 8) * 132 + col) = make_float2(tanh_acc(c[2]), tanh_acc(c[3]));
                }
        }
        __syncthreads();
    }

    // ---- fc: out = h28 @ W_fc^T + b_fc (fp32 SIMT, first 256 threads) ----
    if (tid < 256) {
        const float* h32  = (const float*)smem;
        const float* wfc  = (const float*)(smem + SM_WFC);
        const float* bfcS = (const float*)(smem + SM_BFC);
        int r = tid >> 1;
        int c0 = (tid & 1) * 5;
        float s[5];
        #pragma unroll
        for (int j = 0; j < 5; j++) s[j] = bfcS[c0 + j];
        const float4* hr = (const float4*)(h32 + r * 132);
        #pragma unroll 8
        for (int k4 = 0; k4 < 32; k4++) {
            float4 hv = hr[k4];
            #pragma unroll
            for (int j = 0; j < 5; j++) {
                float4 wv = ((const float4*)(wfc + (c0 + j) * 128))[k4];
                s[j] += hv.x * wv.x + hv.y * wv.y + hv.z * wv.z + hv.w * wv.w;
            }
        }
        float* o = out + ((size_t)blockIdx.x * 128 + r) * 10 + c0;
        #pragma unroll
        for (int j = 0; j < 5; j++) o[j] = s[j];
    }
}

extern "C" void kernel_launch(void* const* d_in, const int* in_sizes, int n_in,
                              void* d_out, int out_size) {
    const float* x   = (const float*)d_in[0];
    const float* Wih = (const float*)d_in[1];
    const float* Whh = (const float*)d_in[2];
    const float* bih = (const float*)d_in[3];
    const float* bhh = (const float*)d_in[4];
    const float* Wfc = (const float*)d_in[5];
    const float* bfc = (const float*)d_in[6];
    float* out = (float*)d_out;

    cudaFuncSetAttribute(SimpleRNN_fused_kernel,
                         cudaFuncAttributeMaxDynamicSharedMemorySize, SM_TOTAL);
    SimpleRNN_fused_kernel<<<128, 512, SM_TOTAL>>>(x, Wih, Whh, bih, bhh, Wfc, bfc, out);
}

// round 5
// speedup vs baseline: 1.9948x; 1.0911x over previous
#include <cuda_runtime.h>
#include <cuda_fp16.h>
#include <cstdint>

// ============================================================================
// SimpleRNN fused kernel: fp16 mma.sync, M=64 per CTA, 2 CTAs/SM for
// cross-CTA overlap of MMA phase and tanh epilogue. Ping-pong H/X buffers
// -> single __syncthreads per timestep.
//   h_{t+1} = tanh(x_t@W_ih^T + b + h_t@W_hh^T), t=0..27; out = h@W_fc^T + b_fc
// Grid: 256 CTAs x 256 threads; CTA = 64 batch rows; warp grid 2m x 4n (32x32).
// ============================================================================

#define SM_WHH 0          // 128 x 128 fp16, row stride 256B, swz ^(row&7)
#define SM_WIH 32768      // 128 x 32 fp16, row stride 64B, swz ^(row&3)
#define SM_H0  40960      // 64 x 128 fp16 (A of hh GEMM), ping
#define SM_H1  57344      // pong
#define SM_X0  73728      // 64 x 32 fp16 (col28 = bias 1.0), ping
#define SM_X1  77824      // pong
#define SM_WFC 81920      // 10 x 128 fp32
#define SM_BFC 87040      // 10 fp32
#define SM_TOTAL 87168
// post-loop alias: fp32 h28 at offset 0, stride 132 floats (64*132*4 < 40960)

static __device__ __forceinline__ uint32_t s2u(const void* p) {
    uint32_t a;
    asm("{ .reg .u64 t; cvta.to.shared.u64 t, %1; cvt.u32.u64 %0, t; }"
        : "=r"(a) : "l"(p));
    return a;
}

// pack two floats -> fp16x2, v0 in low half
static __device__ __forceinline__ uint32_t packh(float v0, float v1) {
    uint32_t r;
    asm("cvt.rn.f16x2.f32 %0, %1, %2;" : "=r"(r) : "f"(v1), "f"(v0));
    return r;
}

// accurate tanh: 1 - 2/(e^{2x}+1)  (~1e-7 abs err)
static __device__ __forceinline__ float tanh_acc(float v) {
    float a = fminf(fmaxf(v * 2.885390082f, -30.0f), 30.0f);
    float e; asm("ex2.approx.f32 %0, %1;" : "=f"(e) : "f"(a));
    float r; asm("rcp.approx.f32 %0, %1;" : "=f"(r) : "f"(e + 1.0f));
    return fmaf(-2.0f, r, 1.0f);
}

#define LDSM4(R, A)                                                              \
    asm volatile("ldmatrix.sync.aligned.m8n8.x4.shared.b16 {%0,%1,%2,%3}, [%4];" \
                 : "=r"((R)[0]), "=r"((R)[1]), "=r"((R)[2]), "=r"((R)[3])        \
                 : "r"(A))

static __device__ __forceinline__ void mma_f16(float* d, const uint32_t* a,
                                               uint32_t b0, uint32_t b1) {
    asm volatile(
        "mma.sync.aligned.m16n8k16.row.col.f32.f16.f16.f32 "
        "{%0,%1,%2,%3}, {%4,%5,%6,%7}, {%8,%9}, {%0,%1,%2,%3};"
        : "+f"(d[0]), "+f"(d[1]), "+f"(d[2]), "+f"(d[3])
        : "r"(a[0]), "r"(a[1]), "r"(a[2]), "r"(a[3]), "r"(b0), "r"(b1));
}

__global__ void __launch_bounds__(256, 2) SimpleRNN_fused_kernel(
    const float* __restrict__ x,    // [16384,1,28,28]
    const float* __restrict__ Wih,  // [128,28]
    const float* __restrict__ Whh,  // [128,128]
    const float* __restrict__ bih,  // [128]
    const float* __restrict__ bhh,  // [128]
    const float* __restrict__ Wfc,  // [10,128]
    const float* __restrict__ bfc,  // [10]
    float* __restrict__ out)        // [16384,10]
{
    extern __shared__ char smem[];
    const uint32_t sb = s2u(smem);
    const int tid  = threadIdx.x;
    const int lane = tid & 31;
    const int wid  = tid >> 5;
    const int m0 = (wid & 1) * 32;   // warp M offset (2 rows of warps)
    const int n0 = (wid >> 1) * 32;  // warp N offset (4 cols of warps)

    // ldmatrix lane addressing
    const int rowA = lane & 15;
    const int csA  = lane >> 4;
    const int rowB = ((lane >> 4) << 3) | (lane & 7);
    const int csB  = (lane >> 3) & 1;
    const int l7 = lane & 7, l3 = lane & 3;

    // ---- one-time: weights -> fp16 swizzled SMEM ----
    for (int i = tid; i < 128 * 128; i += 256) {
        int n = i >> 7, k = i & 127;
        uint32_t byte = (uint32_t)(n * 256 + (((k >> 3) ^ (n & 7)) << 4) + (k & 7) * 2);
        *(uint16_t*)(smem + SM_WHH + byte) = __half_as_ushort(__float2half_rn(Whh[i]));
    }
    for (int i = tid; i < 128 * 32; i += 256) {
        int n = i >> 5, k = i & 31;
        float v = (k < 28) ? Wih[n * 28 + k] : ((k == 28) ? (bih[n] + bhh[n]) : 0.0f);
        uint32_t byte = (uint32_t)(n * 64 + (((k >> 3) ^ (n & 3)) << 4) + (k & 7) * 2);
        *(uint16_t*)(smem + SM_WIH + byte) = __half_as_ushort(__float2half_rn(v));
    }
    for (int i = tid; i < 1280; i += 256) ((float*)(smem + SM_WFC))[i] = Wfc[i];
    if (tid < 10) ((float*)(smem + SM_BFC))[tid] = bfc[tid];

    // ---- x layout: row r = tid>>2 (0..63), col chunk q = tid&3 ----
    const int xr = tid >> 2, xq = tid & 3;
    const size_t xbase = ((size_t)blockIdx.x * 64 + xr) * 784 + (size_t)xq * 8;
    const uint32_t xoff = (uint32_t)(xr * 64 + ((xq ^ (xr & 3)) << 4));
    float xf[8];
    {
        const float4* px = (const float4*)(x + xbase);
        float4 v0 = px[0];
        xf[0]=v0.x; xf[1]=v0.y; xf[2]=v0.z; xf[3]=v0.w;
        if (xq < 3) { float4 v1 = px[1]; xf[4]=v1.x; xf[5]=v1.y; xf[6]=v1.z; xf[7]=v1.w; }
    }
    {
        uint32_t p0 = packh(xf[0], xf[1]), p1 = packh(xf[2], xf[3]);
        uint32_t p2, p3;
        if (xq < 3) { p2 = packh(xf[4], xf[5]); p3 = packh(xf[6], xf[7]); }
        else        { p2 = 0x00003C00u; p3 = 0u; }  // col28 = 1.0 bias
        asm volatile("st.shared.v4.b32 [%0], {%1,%2,%3,%4};"
                     :: "r"(sb + SM_X0 + xoff), "r"(p0), "r"(p1), "r"(p2), "r"(p3) : "memory");
    }
    __syncthreads();

    float acc[2][4][4];

    #pragma unroll 1
    for (int t = 0; t < 28; t++) {
        const uint32_t Hrd = (t & 1) ? SM_H1 : SM_H0;   // read h(t)
        const uint32_t Hwr = (t & 1) ? SM_H0 : SM_H1;   // write h(t+1)
        const uint32_t Xrd = (t & 1) ? SM_X1 : SM_X0;
        const uint32_t Xwr = (t & 1) ? SM_X0 : SM_X1;

        #pragma unroll
        for (int mt = 0; mt < 2; mt++)
            #pragma unroll
            for (int nt = 0; nt < 4; nt++)
                #pragma unroll
                for (int j = 0; j < 4; j++) acc[mt][nt][j] = 0.0f;

        // ---- x GEMM (K=32) ----
        #pragma unroll
        for (int kt = 0; kt < 2; kt++) {
            uint32_t A[2][4], B[2][4];
            #pragma unroll
            for (int mt = 0; mt < 2; mt++) {
                uint32_t ro = (uint32_t)((m0 + mt * 16 + rowA) * 64 + (((kt * 2 + csA) ^ l3) << 4));
                LDSM4(A[mt], sb + Xrd + ro);
            }
            #pragma unroll
            for (int nt = 0; nt < 2; nt++) {
                uint32_t ro = (uint32_t)((n0 + nt * 16 + rowB) * 64 + (((kt * 2 + csB) ^ l3) << 4));
                LDSM4(B[nt], sb + SM_WIH + ro);
            }
            #pragma unroll
            for (int mt = 0; mt < 2; mt++)
                #pragma unroll
                for (int nt = 0; nt < 2; nt++) {
                    mma_f16(acc[mt][2*nt],   A[mt], B[nt][0], B[nt][1]);
                    mma_f16(acc[mt][2*nt+1], A[mt], B[nt][2], B[nt][3]);
                }
        }

        // ---- hh GEMM (K=128), skip at t=0 ----
        if (t > 0) {
            #pragma unroll
            for (int kt = 0; kt < 8; kt++) {
                uint32_t A[2][4], B[2][4];
                #pragma unroll
                for (int mt = 0; mt < 2; mt++) {
                    uint32_t ro = (uint32_t)((m0 + mt * 16 + rowA) * 256 + (((kt * 2 + csA) ^ l7) << 4));
                    LDSM4(A[mt], sb + Hrd + ro);
                }
                #pragma unroll
                for (int nt = 0; nt < 2; nt++) {
                    uint32_t ro = (uint32_t)((n0 + nt * 16 + rowB) * 256 + (((kt * 2 + csB) ^ l7) << 4));
                    LDSM4(B[nt], sb + SM_WHH + ro);
                }
                #pragma unroll
                for (int mt = 0; mt < 2; mt++)
                    #pragma unroll
                    for (int nt = 0; nt < 2; nt++) {
                        mma_f16(acc[mt][2*nt],   A[mt], B[nt][0], B[nt][1]);
                        mma_f16(acc[mt][2*nt+1], A[mt], B[nt][2], B[nt][3]);
                    }
            }
        }

        if (t < 27) {
            // prefetch x(t+1)
            const float4* px = (const float4*)(x + xbase + (size_t)(t + 1) * 28);
            float4 v0 = px[0];
            xf[0]=v0.x; xf[1]=v0.y; xf[2]=v0.z; xf[3]=v0.w;
            if (xq < 3) { float4 v1 = px[1]; xf[4]=v1.x; xf[5]=v1.y; xf[6]=v1.z; xf[7]=v1.w; }

            // h(t+1) = tanh(acc) -> fp16 into Hwr (no barrier needed: disjoint buffer)
            #pragma unroll
            for (int mt = 0; mt < 2; mt++)
                #pragma unroll
                for (int nt = 0; nt < 4; nt++) {
                    const float* c = acc[mt][nt];
                    int r0 = m0 + mt * 16 + (lane >> 2);
                    int r1 = r0 + 8;
                    int chunk = (n0 >> 3) + nt;
                    uint32_t b0 = (uint32_t)(r0 * 256 + ((chunk ^ (r0 & 7)) << 4) + (lane & 3) * 4);
                    uint32_t b1 = (uint32_t)(r1 * 256 + ((chunk ^ (r1 & 7)) << 4) + (lane & 3) * 4);
                    *(uint32_t*)(smem + Hwr + b0) = packh(tanh_acc(c[0]), tanh_acc(c[1]));
                    *(uint32_t*)(smem + Hwr + b1) = packh(tanh_acc(c[2]), tanh_acc(c[3]));
                }
            // store x(t+1) into Xwr
            uint32_t p0 = packh(xf[0], xf[1]), p1 = packh(xf[2], xf[3]);
            uint32_t p2, p3;
            if (xq < 3) { p2 = packh(xf[4], xf[5]); p3 = packh(xf[6], xf[7]); }
            else        { p2 = 0x00003C00u; p3 = 0u; }
            asm volatile("st.shared.v4.b32 [%0], {%1,%2,%3,%4};"
                         :: "r"(sb + Xwr + xoff), "r"(p0), "r"(p1), "r"(p2), "r"(p3) : "memory");
        } else {
            // final step writes fp32 h28 over dead W_hh region -> barrier first
            __syncthreads();
            float* h32 = (float*)smem;
            #pragma unroll
            for (int mt = 0; mt < 2; mt++)
                #pragma unroll
                for (int nt = 0; nt < 4; nt++) {
                    const float* c = acc[mt][nt];
                    int r0 = m0 + mt * 16 + (lane >> 2);
                    int col = n0 + nt * 8 + (lane & 3) * 2;
                    *(float2*)(h32 + r0 * 132 + col)       = make_float2(tanh_acc(c[0]), tanh_acc(c[1]));
                    *(float2*)(h32 + (r0 + 8) * 132 + col) = make_float2(tanh_acc(c[2]), tanh_acc(c[3]));
                }
        }
        __syncthreads();  // writes of this step visible before next step's reads
    }

    // ---- fc: out = h28 @ W_fc^T + b_fc (fp32 SIMT, 128 threads) ----
    if (tid < 128) {
        const float* h32  = (const float*)smem;
        const float* wfc  = (const float*)(smem + SM_WFC);
        const float* bfcS = (const float*)(smem + SM_BFC);
        int r = tid >> 1;
        int c0 = (tid & 1) * 5;
        float s[5];
        #pragma unroll
        for (int j = 0; j < 5; j++) s[j] = bfcS[c0 + j];
        const float4* hr = (const float4*)(h32 + r * 132);
        #pragma unroll 8
        for (int k4 = 0; k4 < 32; k4++) {
            float4 hv = hr[k4];
            #pragma unroll
            for (int j = 0; j < 5; j++) {
                float4 wv = ((const float4*)(wfc + (c0 + j) * 128))[k4];
                s[j] += hv.x * wv.x + hv.y * wv.y + hv.z * wv.z + hv.w * wv.w;
            }
        }
        float* o = out + ((size_t)blockIdx.x * 64 + r) * 10 + c0;
        #pragma unroll
        for (int j = 0; j < 5; j++) o[j] = s[j];
    }
}

extern "C" void kernel_launch(void* const* d_in, const int* in_sizes, int n_in,
                              void* d_out, int out_size) {
    const float* x   = (const float*)d_in[0];
    const float* Wih = (const float*)d_in[1];
    const float* Whh = (const float*)d_in[2];
    const float* bih = (const float*)d_in[3];
    const float* bhh = (const float*)d_in[4];
    const float* Wfc = (const float*)d_in[5];
    const float* bfc = (const float*)d_in[6];
    float* out = (float*)d_out;

    cudaFuncSetAttribute(SimpleRNN_fused_kernel,
                         cudaFuncAttributeMaxDynamicSharedMemorySize, SM_TOTAL);
    SimpleRNN_fused_kernel<<<256, 256, SM_TOTAL>>>(x, Wih, Whh, bih, bhh, Wfc, bfc, out);
}